// round 1
// baseline (speedup 1.0000x reference)
#include <cuda_runtime.h>
#include <math.h>

// Problem dims (fixed by the reference)
#define TT 128
#define NN 1024
#define HH 512
#define II 64

// Tiling
#define BM 64
#define BN 64
#define BK 32
#define TM 4
#define TN 4
#define NTHREADS 256   // 16 x 16

__device__ __forceinline__ float sigmoidf_(float x) {
    return 1.0f / (1.0f + expf(-x));
}

// One GEMM phase: accumulate A[row, k] * B[g*HH + col, k] over KTOT.
//   acc[0] += r-gate, acc[1] += z-gate, acc[ACCN] += n-gate (2 = hidden part, 3 = input part)
// A rows are scaled by mask m_t[row] on load.
template <int KTOT, int ACCN>
__device__ __forceinline__ void gemm_phase(
    const float* __restrict__ Aptr,   // [NN, KTOT]
    const float* __restrict__ Bptr,   // [3*HH, KTOT]
    const float* __restrict__ m_t,    // [NN]
    int rowBase, int colBase, int tid, int tx, int ty,
    float (&acc)[4][TM][TN],
    float (*As)[BM + 4],              // [BK][BM+4]  A^T (masked)
    float (*Bs)[BK][BN + 4])          // [3][BK][BN+4]  B^T per gate
{
    for (int k0 = 0; k0 < KTOT; k0 += BK) {
        __syncthreads();
        // ---- load A tile (transposed into smem), row-scaled by mask ----
        #pragma unroll
        for (int r = 0; r < 2; r++) {
            int idx = r * NTHREADS + tid;      // float4 index, 0..511
            int m   = idx >> 3;                // 0..63
            int kq  = (idx & 7) * 4;           // 0,4,...,28
            float4 v = *reinterpret_cast<const float4*>(
                &Aptr[(size_t)(rowBase + m) * KTOT + k0 + kq]);
            float mm = m_t[rowBase + m];
            As[kq + 0][m] = v.x * mm;
            As[kq + 1][m] = v.y * mm;
            As[kq + 2][m] = v.z * mm;
            As[kq + 3][m] = v.w * mm;
        }
        // ---- load B tiles for 3 gates (transposed into smem) ----
        #pragma unroll
        for (int g = 0; g < 3; g++) {
            #pragma unroll
            for (int r = 0; r < 2; r++) {
                int idx = r * NTHREADS + tid;
                int c   = idx >> 3;            // 0..63
                int kq  = (idx & 7) * 4;
                float4 v = *reinterpret_cast<const float4*>(
                    &Bptr[(size_t)(g * HH + colBase + c) * KTOT + k0 + kq]);
                Bs[g][kq + 0][c] = v.x;
                Bs[g][kq + 1][c] = v.y;
                Bs[g][kq + 2][c] = v.z;
                Bs[g][kq + 3][c] = v.w;
            }
        }
        __syncthreads();

        // ---- compute ----
        #pragma unroll
        for (int k = 0; k < BK; k++) {
            float a[TM];
            #pragma unroll
            for (int i = 0; i < TM; i++) a[i] = As[k][ty * TM + i];
            float br[TN], bz[TN], bn[TN];
            #pragma unroll
            for (int j = 0; j < TN; j++) {
                br[j] = Bs[0][k][tx * TN + j];
                bz[j] = Bs[1][k][tx * TN + j];
                bn[j] = Bs[2][k][tx * TN + j];
            }
            #pragma unroll
            for (int i = 0; i < TM; i++) {
                #pragma unroll
                for (int j = 0; j < TN; j++) {
                    acc[0][i][j]    = fmaf(a[i], br[j], acc[0][i][j]);
                    acc[1][i][j]    = fmaf(a[i], bz[j], acc[1][i][j]);
                    acc[ACCN][i][j] = fmaf(a[i], bn[j], acc[ACCN][i][j]);
                }
            }
        }
    }
}

// One GRU step, fully fused: (h*m) @ W_hh^T + (x*m) @ W_ih^T -> gates -> h_new
__global__ __launch_bounds__(NTHREADS)
void gru_step_kernel(const float* __restrict__ h_prev,  // [NN, HH]
                     const float* __restrict__ x_t,     // [NN, II]
                     const float* __restrict__ m_t,     // [NN]
                     const float* __restrict__ W_ih,    // [3*HH, II]
                     const float* __restrict__ W_hh,    // [3*HH, HH]
                     const float* __restrict__ b_ih,    // [3*HH]
                     const float* __restrict__ b_hh,    // [3*HH]
                     float* __restrict__ h_out,         // [NN, HH]
                     float* __restrict__ h_out2)        // dup (final h) or null
{
    __shared__ float As[BK][BM + 4];
    __shared__ float Bs[3][BK][BN + 4];

    const int tid = threadIdx.x;
    const int tx  = tid & 15;   // output column group
    const int ty  = tid >> 4;   // output row group
    const int rowBase = blockIdx.y * BM;
    const int colBase = blockIdx.x * BN;

    // acc[0]=r (x+h), acc[1]=z (x+h), acc[2]=h_n (hidden only), acc[3]=i_n (input only)
    float acc[4][TM][TN];
    #pragma unroll
    for (int g = 0; g < 4; g++)
        #pragma unroll
        for (int i = 0; i < TM; i++)
            #pragma unroll
            for (int j = 0; j < TN; j++)
                acc[g][i][j] = 0.0f;

    // Hidden phase (K = 512), n-gate into acc[2]
    gemm_phase<HH, 2>(h_prev, W_hh, m_t, rowBase, colBase, tid, tx, ty, acc, As, Bs);
    // Input phase (K = 64), n-gate into acc[3]
    gemm_phase<II, 3>(x_t,   W_ih, m_t, rowBase, colBase, tid, tx, ty, acc, As, Bs);

    // ---- epilogue: gates ----
    #pragma unroll
    for (int i = 0; i < TM; i++) {
        const int n  = rowBase + ty * TM + i;
        const float mm = m_t[n];
        #pragma unroll
        for (int j = 0; j < TN; j++) {
            const int c = colBase + tx * TN + j;
            const float hm = h_prev[(size_t)n * HH + c] * mm;   // masked h (leak term)
            const float r  = sigmoidf_(acc[0][i][j] + b_ih[c]          + b_hh[c]);
            const float z  = sigmoidf_(acc[1][i][j] + b_ih[HH + c]     + b_hh[HH + c]);
            const float ng = tanhf(acc[3][i][j] + b_ih[2 * HH + c]
                                   + r * (acc[2][i][j] + b_hh[2 * HH + c]));
            const float hv = (1.0f - z) * ng + z * hm;
            h_out[(size_t)n * HH + c] = hv;
            if (h_out2) h_out2[(size_t)n * HH + c] = hv;
        }
    }
}

extern "C" void kernel_launch(void* const* d_in, const int* in_sizes, int n_in,
                              void* d_out, int out_size) {
    // Input order per setup_inputs():
    // 0: hxs [N,H], 1: gru_init (dead), 2: masks [T*N,1], 3: prev_action_one_hot [T,N,I],
    // 4: W_ih [3H,I], 5: W_hh [3H,H], 6: b_ih [3H], 7: b_hh [3H]
    const float* hxs   = (const float*)d_in[0];
    const float* masks = (const float*)d_in[2];
    const float* pact  = (const float*)d_in[3];
    const float* W_ih  = (const float*)d_in[4];
    const float* W_hh  = (const float*)d_in[5];
    const float* b_ih  = (const float*)d_in[6];
    const float* b_hh  = (const float*)d_in[7];
    float* out = (float*)d_out;

    const size_t stepElems = (size_t)NN * HH;
    const bool has_tail = (size_t)out_size >= (size_t)TT * stepElems + stepElems;

    dim3 grid(HH / BN, NN / BM);   // (8, 16) = 128 blocks
    for (int t = 0; t < TT; t++) {
        const float* h_prev = (t == 0) ? hxs : out + (size_t)(t - 1) * stepElems;
        float* h_out  = out + (size_t)t * stepElems;
        float* h_out2 = (t == TT - 1 && has_tail) ? out + (size_t)TT * stepElems
                                                  : nullptr;
        gru_step_kernel<<<grid, NTHREADS>>>(
            h_prev,
            pact + (size_t)t * NN * II,
            masks + (size_t)t * NN,
            W_ih, W_hh, b_ih, b_hh,
            h_out, h_out2);
    }
}

// round 4
// speedup vs baseline: 2.5320x; 2.5320x over previous
#include <cuda_runtime.h>
#include <math.h>
#include <stdint.h>

// ---------------- problem dims ----------------
#define TT 128
#define NN 1024
#define HH 512
#define II 64
#define G3 1536            // 3*HH

// ---------------- device scratch ----------------
__device__ float g_Whh_t[8 * 192 * HH];          // strip-ordered, tf32-rounded
__device__ float g_Wih_t[G3 * II];               // tf32-rounded
__device__ float g_hA[2][NN * HH];               // tf32 h ping-pong (A operand)
__device__ float g_Gi[(size_t)TT * NN * G3];     // precomputed x @ W_ih^T (805 MB)

// ---------------- helpers ----------------
__device__ __forceinline__ uint32_t f2tf32(float f) {
    uint32_t r;
    asm("cvt.rna.tf32.f32 %0, %1;" : "=r"(r) : "f"(f));
    return r;
}
__device__ __forceinline__ uint32_t smem_u32(const void* p) {
    uint32_t a;
    asm("{ .reg .u64 t; cvta.to.shared.u64 t, %1; cvt.u32.u64 %0, t; }" : "=r"(a) : "l"(p));
    return a;
}
__device__ __forceinline__ float sigf(float x) {
    return 1.0f / (1.0f + __expf(-x));
}

#define CP_ASYNC16(dst, src) \
    asm volatile("cp.async.cg.shared.global [%0], [%1], 16;" :: "r"(dst), "l"(src))
#define CP_COMMIT() asm volatile("cp.async.commit_group;" ::: "memory")

__device__ __forceinline__ void mma_tf32(float (&c)[4], const uint32_t (&a)[4],
                                         const uint32_t (&b)[2]) {
    asm volatile(
        "mma.sync.aligned.m16n8k8.row.col.f32.tf32.tf32.f32 "
        "{%0,%1,%2,%3}, {%4,%5,%6,%7}, {%8,%9}, {%0,%1,%2,%3};"
        : "+f"(c[0]), "+f"(c[1]), "+f"(c[2]), "+f"(c[3])
        : "r"(a[0]), "r"(a[1]), "r"(a[2]), "r"(a[3]), "r"(b[0]), "r"(b[1]));
}

// ================= prep: tf32-round weights (strip layout) + hxs =================
__global__ void prep_kernel(const float* __restrict__ W_hh,
                            const float* __restrict__ W_ih,
                            const float* __restrict__ hxs) {
    int idx = blockIdx.x * blockDim.x + threadIdx.x;
    if (idx < G3 * HH) {
        int r = idx >> 9, k = idx & 511;
        int g = r >> 9, u = r & 511, s = u >> 6, c = u & 63;
        g_Whh_t[((size_t)(s * 192 + (g << 6) + c)) * HH + k] =
            __uint_as_float(f2tf32(W_hh[idx]));
    }
    if (idx < G3 * II) g_Wih_t[idx] = __uint_as_float(f2tf32(W_ih[idx]));
    if (idx < NN * HH) g_hA[0][idx] = __uint_as_float(f2tf32(hxs[idx]));
}

// ================= Gi precompute: Gi[T*N, 1536] = X[T*N,64] @ W_ih^T =============
#define GI_SST 68
__global__ __launch_bounds__(256, 1)
void gi_kernel(const float* __restrict__ X) {
    extern __shared__ float sm[];
    float* Xs = sm;                    // [128][GI_SST]
    float* Ws = sm + 128 * GI_SST;     // [128][GI_SST]
    const int tid = threadIdx.x;
    const int rb = blockIdx.y * 128;
    const int cb = blockIdx.x * 128;

    #pragma unroll
    for (int it = 0; it < 8; it++) {
        int id = it * 256 + tid;           // 0..2047 float4 slots
        int row = id >> 4, c4 = (id & 15) * 4;
        float4 v = *reinterpret_cast<const float4*>(X + (size_t)(rb + row) * II + c4);
        uint4 o = make_uint4(f2tf32(v.x), f2tf32(v.y), f2tf32(v.z), f2tf32(v.w));
        *reinterpret_cast<uint4*>(Xs + row * GI_SST + c4) = o;
        float4 w = *reinterpret_cast<const float4*>(g_Wih_t + (size_t)(cb + row) * II + c4);
        *reinterpret_cast<float4*>(Ws + row * GI_SST + c4) = w;
    }
    __syncthreads();

    const int w = tid >> 5, lane = tid & 31, g = lane >> 2, t = lane & 3;
    const int wr = w & 3, wc = w >> 2;   // 4 row groups x 2 col groups
    float acc[2][8][4];
    #pragma unroll
    for (int sl = 0; sl < 2; sl++)
        #pragma unroll
        for (int j = 0; j < 8; j++)
            #pragma unroll
            for (int q = 0; q < 4; q++) acc[sl][j][q] = 0.0f;

    #pragma unroll
    for (int k8 = 0; k8 < 8; k8++) {
        const int kb = k8 * 8;
        uint32_t a[2][4], b[8][2];
        #pragma unroll
        for (int sl = 0; sl < 2; sl++) {
            int m0 = wr * 32 + sl * 16;
            a[sl][0] = __float_as_uint(Xs[(m0 + g) * GI_SST + kb + t]);
            a[sl][1] = __float_as_uint(Xs[(m0 + 8 + g) * GI_SST + kb + t]);
            a[sl][2] = __float_as_uint(Xs[(m0 + g) * GI_SST + kb + t + 4]);
            a[sl][3] = __float_as_uint(Xs[(m0 + 8 + g) * GI_SST + kb + t + 4]);
        }
        #pragma unroll
        for (int j = 0; j < 8; j++) {
            int n0 = wc * 64 + j * 8;
            b[j][0] = __float_as_uint(Ws[(n0 + g) * GI_SST + kb + t]);
            b[j][1] = __float_as_uint(Ws[(n0 + g) * GI_SST + kb + t + 4]);
        }
        #pragma unroll
        for (int sl = 0; sl < 2; sl++)
            #pragma unroll
            for (int j = 0; j < 8; j++) mma_tf32(acc[sl][j], a[sl], b[j]);
    }

    #pragma unroll
    for (int sl = 0; sl < 2; sl++) {
        #pragma unroll
        for (int j = 0; j < 8; j++) {
            int row = rb + wr * 32 + sl * 16 + g;
            int col = cb + wc * 64 + j * 8 + 2 * t;
            *reinterpret_cast<float2*>(g_Gi + (size_t)row * G3 + col) =
                make_float2(acc[sl][j][0], acc[sl][j][1]);
            *reinterpret_cast<float2*>(g_Gi + (size_t)(row + 8) * G3 + col) =
                make_float2(acc[sl][j][2], acc[sl][j][3]);
        }
    }
}

// ================= per-step kernel: S = h @ W_hh^T, gates, h_new =================
#define SAST 36
#define ABUF_B (64 * SAST * 4)            // 9216
#define BBUF_B (192 * SAST * 4)           // 27648
#define STAGE_B (ABUF_B + BBUF_B)         // 36864
#define SMEM_STEP (3 * STAGE_B)           // 110592
#define SST 196
#define NSTG 16

__device__ __forceinline__ void issue_stage(int stg, uint32_t sbase,
                                            const float* __restrict__ hA,
                                            int rb, int strip, int tid) {
    const int k0 = stg * 32;
    const uint32_t abase = sbase + (stg % 3) * STAGE_B;
    #pragma unroll
    for (int it = 0; it < 2; it++) {
        int id = it * 256 + tid;            // 0..511
        int row = id >> 3, c = id & 7;
        CP_ASYNC16(abase + row * (SAST * 4) + c * 16,
                   hA + (size_t)(rb + row) * HH + k0 + c * 4);
    }
    const uint32_t bbase = abase + ABUF_B;
    const float* wsrc = g_Whh_t + (size_t)strip * 192 * HH + k0;
    #pragma unroll
    for (int it = 0; it < 6; it++) {
        int id = it * 256 + tid;            // 0..1535
        int row = id >> 3, c = id & 7;
        CP_ASYNC16(bbase + row * (SAST * 4) + c * 16,
                   wsrc + (size_t)row * HH + c * 4);
    }
}

__global__ __launch_bounds__(256, 1)
void gru_step(const float* __restrict__ hA,       // tf32 h (prev), [NN,HH]
              float* __restrict__ hA_next,        // tf32 h (new)
              const float* __restrict__ h_prev,   // fp32 h (prev)
              const float* __restrict__ m_t,      // [NN]
              const float* __restrict__ Gi_t,     // [NN, G3]
              const float* __restrict__ b_ih,
              const float* __restrict__ b_hh,
              float* __restrict__ h_out,
              float* __restrict__ h_out2) {
    extern __shared__ char smem[];
    const uint32_t sbase = smem_u32(smem);
    const int tid = threadIdx.x;
    const int strip = blockIdx.x;             // 0..7 -> gate cols strip*64..
    const int rb = blockIdx.y * 64;

    const int w = tid >> 5, lane = tid & 31, g = lane >> 2, t = lane & 3;
    const int wr = w & 1, wc = w >> 1;        // 2 row groups x 4 col groups

    float acc[2][6][4];
    #pragma unroll
    for (int sl = 0; sl < 2; sl++)
        #pragma unroll
        for (int j = 0; j < 6; j++)
            #pragma unroll
            for (int q = 0; q < 4; q++) acc[sl][j][q] = 0.0f;

    issue_stage(0, sbase, hA, rb, strip, tid); CP_COMMIT();
    issue_stage(1, sbase, hA, rb, strip, tid); CP_COMMIT();

    for (int stg = 0; stg < NSTG; stg++) {
        if (stg < NSTG - 2) asm volatile("cp.async.wait_group 1;" ::: "memory");
        else                asm volatile("cp.async.wait_group 0;" ::: "memory");
        __syncthreads();
        if (stg + 2 < NSTG) { issue_stage(stg + 2, sbase, hA, rb, strip, tid); CP_COMMIT(); }

        const float* As = (const float*)(smem + (stg % 3) * STAGE_B);
        const float* Bs = (const float*)(smem + (stg % 3) * STAGE_B + ABUF_B);
        #pragma unroll
        for (int k8 = 0; k8 < 4; k8++) {
            const int kb = k8 * 8;
            uint32_t a[2][4], b[6][2];
            #pragma unroll
            for (int sl = 0; sl < 2; sl++) {
                int m0 = wr * 32 + sl * 16;
                a[sl][0] = __float_as_uint(As[(m0 + g) * SAST + kb + t]);
                a[sl][1] = __float_as_uint(As[(m0 + 8 + g) * SAST + kb + t]);
                a[sl][2] = __float_as_uint(As[(m0 + g) * SAST + kb + t + 4]);
                a[sl][3] = __float_as_uint(As[(m0 + 8 + g) * SAST + kb + t + 4]);
            }
            #pragma unroll
            for (int j = 0; j < 6; j++) {
                int n0 = wc * 48 + j * 8;
                b[j][0] = __float_as_uint(Bs[(n0 + g) * SAST + kb + t]);
                b[j][1] = __float_as_uint(Bs[(n0 + g) * SAST + kb + t + 4]);
            }
            #pragma unroll
            for (int sl = 0; sl < 2; sl++)
                #pragma unroll
                for (int j = 0; j < 6; j++) mma_tf32(acc[sl][j], a[sl], b[j]);
        }
    }

    // ---- stage S through smem so each thread sees r,z,n of its output cols ----
    __syncthreads();
    float* Ssh = (float*)smem;   // [64][SST], reuses pipeline buffers
    #pragma unroll
    for (int sl = 0; sl < 2; sl++) {
        #pragma unroll
        for (int j = 0; j < 6; j++) {
            int r0 = wr * 32 + sl * 16 + g;
            int c0 = wc * 48 + j * 8 + 2 * t;
            *reinterpret_cast<float2*>(&Ssh[r0 * SST + c0]) =
                make_float2(acc[sl][j][0], acc[sl][j][1]);
            *reinterpret_cast<float2*>(&Ssh[(r0 + 8) * SST + c0]) =
                make_float2(acc[sl][j][2], acc[sl][j][3]);
        }
    }
    __syncthreads();

    // ---- gates + mask + store (thread: 1 row x 16 cols) ----
    {
        const int row_l = tid >> 2;
        const int cb_l = (tid & 3) * 16;
        const int grow = rb + row_l;
        const int gcol0 = strip * 64 + cb_l;
        const float m = m_t[grow];
        const float* giRow = Gi_t + (size_t)grow * G3 + gcol0;
        const float* hpRow = h_prev + (size_t)grow * HH + gcol0;
        float* o1 = h_out + (size_t)grow * HH + gcol0;
        float* o2 = h_out2 ? h_out2 + (size_t)grow * HH + gcol0 : nullptr;
        float* oa = hA_next + (size_t)grow * HH + gcol0;

        #pragma unroll
        for (int q = 0; q < 4; q++) {
            const int c = cb_l + q * 4;
            float4 Sr = *reinterpret_cast<const float4*>(&Ssh[row_l * SST + c]);
            float4 Sz = *reinterpret_cast<const float4*>(&Ssh[row_l * SST + 64 + c]);
            float4 Sn = *reinterpret_cast<const float4*>(&Ssh[row_l * SST + 128 + c]);
            float4 Gr = *reinterpret_cast<const float4*>(giRow + q * 4);
            float4 Gz = *reinterpret_cast<const float4*>(giRow + 512 + q * 4);
            float4 Gn = *reinterpret_cast<const float4*>(giRow + 1024 + q * 4);
            float4 br1 = *reinterpret_cast<const float4*>(b_ih + gcol0 + q * 4);
            float4 bz1 = *reinterpret_cast<const float4*>(b_ih + 512 + gcol0 + q * 4);
            float4 bn1 = *reinterpret_cast<const float4*>(b_ih + 1024 + gcol0 + q * 4);
            float4 br2 = *reinterpret_cast<const float4*>(b_hh + gcol0 + q * 4);
            float4 bz2 = *reinterpret_cast<const float4*>(b_hh + 512 + gcol0 + q * 4);
            float4 bn2 = *reinterpret_cast<const float4*>(b_hh + 1024 + gcol0 + q * 4);
            float4 hp = *reinterpret_cast<const float4*>(hpRow + q * 4);

            float hv[4];
            const float* sr = &Sr.x; const float* sz = &Sz.x; const float* sn = &Sn.x;
            const float* gr = &Gr.x; const float* gz = &Gz.x; const float* gn = &Gn.x;
            const float* p1 = &br1.x; const float* p2 = &bz1.x; const float* p3 = &bn1.x;
            const float* p4 = &br2.x; const float* p5 = &bz2.x; const float* p6 = &bn2.x;
            const float* ph = &hp.x;
            #pragma unroll
            for (int e = 0; e < 4; e++) {
                float r = sigf(fmaf(m, sr[e] + gr[e], p1[e] + p4[e]));
                float z = sigf(fmaf(m, sz[e] + gz[e], p2[e] + p5[e]));
                float n = tanhf(fmaf(m, gn[e], p3[e]) + r * fmaf(m, sn[e], p6[e]));
                hv[e] = fmaf(z, fmaf(m, ph[e], -n), n);   // n + z*(m*h - n)
            }
            float4 o = make_float4(hv[0], hv[1], hv[2], hv[3]);
            *reinterpret_cast<float4*>(o1 + q * 4) = o;
            if (o2) *reinterpret_cast<float4*>(o2 + q * 4) = o;
            uint4 oc = make_uint4(f2tf32(hv[0]), f2tf32(hv[1]), f2tf32(hv[2]), f2tf32(hv[3]));
            *reinterpret_cast<uint4*>(oa + q * 4) = oc;
        }
    }
}

// ---------------- host ----------------
extern "C" void kernel_launch(void* const* d_in, const int* in_sizes, int n_in,
                              void* d_out, int out_size) {
    const float* hxs   = (const float*)d_in[0];
    const float* masks = (const float*)d_in[2];
    const float* pact  = (const float*)d_in[3];
    const float* W_ih  = (const float*)d_in[4];
    const float* W_hh  = (const float*)d_in[5];
    const float* b_ih  = (const float*)d_in[6];
    const float* b_hh  = (const float*)d_in[7];
    float* out = (float*)d_out;

    static bool attr_set = false;
    if (!attr_set) {
        cudaFuncSetAttribute(gi_kernel, cudaFuncAttributeMaxDynamicSharedMemorySize,
                             2 * 128 * GI_SST * 4);
        cudaFuncSetAttribute(gru_step, cudaFuncAttributeMaxDynamicSharedMemorySize,
                             SMEM_STEP);
        attr_set = true;
    }

    // Resolve device addresses of __device__ symbols (host shadow address is NOT
    // a device pointer!). Cached after first resolution; queries are capture-safe.
    static float* hA0 = nullptr;
    static float* gGi = nullptr;
    if (!hA0) cudaGetSymbolAddress((void**)&hA0, g_hA);
    if (!gGi) cudaGetSymbolAddress((void**)&gGi, g_Gi);

    // 1) weight/hxs prep
    prep_kernel<<<(G3 * HH + 255) / 256, 256>>>(W_hh, W_ih, hxs);

    // 2) Gi = X @ W_ih^T for all T*N rows
    {
        dim3 grid(G3 / 128, (TT * NN) / 128);    // (12, 1024)
        gi_kernel<<<grid, 256, 2 * 128 * GI_SST * 4>>>(pact);
    }

    // 3) 128 sequential GRU steps
    const size_t stepElems = (size_t)NN * HH;
    const bool has_tail = (size_t)out_size >= (size_t)TT * stepElems + stepElems;

    dim3 grid(8, NN / 64);                       // (8, 16) = 128 CTAs
    for (int tstep = 0; tstep < TT; tstep++) {
        const float* h_prev = (tstep == 0) ? hxs : out + (size_t)(tstep - 1) * stepElems;
        float* h_out  = out + (size_t)tstep * stepElems;
        float* h_out2 = (tstep == TT - 1 && has_tail) ? out + (size_t)TT * stepElems
                                                      : nullptr;
        const float* hA_cur  = hA0 + (size_t)(tstep & 1) * NN * HH;
        float*       hA_next = hA0 + (size_t)((tstep + 1) & 1) * NN * HH;
        gru_step<<<grid, 256, SMEM_STEP>>>(
            hA_cur, hA_next, h_prev,
            masks + (size_t)tstep * NN,
            gGi + (size_t)tstep * NN * G3,
            b_ih, b_hh, h_out, h_out2);
    }
}